// round 8
// baseline (speedup 1.0000x reference)
#include <cuda_runtime.h>
#include <math.h>

#define BATCH 2
#define CH    64
#define HH    112
#define WW    112
#define HWSZ  (HH*WW)
#define NPIX  (BATCH*HWSZ)
#define RAD   3
#define NN    49
#define NPAD  52

__device__ __align__(256) float g_px  [NPIX*CH];    // range-projected, NHWC
__device__ __align__(256) float g_spat[NPIX*CH];    // spatial feats, NHWC
__device__ __align__(256) float g_mid [NPIX*CH];    // pre-output_proj, NHWC
__device__ __align__(256) float g_fxs [NPIX*CH];    // fixup semantic partial (64-pad)
__device__ __align__(256) float g_comb[NPIX*NPAD];  // bilateral weights (52-pad)

__device__ __forceinline__ float grp16_sum(float v) {
#pragma unroll
    for (int off = 8; off > 0; off >>= 1)
        v += __shfl_xor_sync(0xffffffffu, v, off);
    return v;
}
__device__ __forceinline__ float sigmf(float x) {
    return 1.f / (1.f + __expf(-x));
}

#define FMA4W(Acc, W, X) { \
    Acc.x = fmaf(W.x, X, Acc.x); Acc.y = fmaf(W.y, X, Acc.y); \
    Acc.z = fmaf(W.z, X, Acc.z); Acc.w = fmaf(W.w, X, Acc.w); }

__device__ __forceinline__ float4 ln_apply(float4 A, float4 g, float4 be, float invn) {
    float s1 = grp16_sum(A.x + A.y + A.z + A.w);
    float s2 = grp16_sum(A.x*A.x + A.y*A.y + A.z*A.z + A.w*A.w);
    float u  = s1 * invn;
    float rs = rsqrtf(fmaxf(s2 * invn - u * u, 0.f) + 1e-6f);
    return make_float4(fmaf(g.x, (A.x - u) * rs, be.x),
                       fmaf(g.y, (A.y - u) * rs, be.y),
                       fmaf(g.z, (A.z - u) * rs, be.z),
                       fmaf(g.w, (A.w - u) * rs, be.w));
}
__device__ __forceinline__ float4 silu4(float4 v) {
    return make_float4(v.x * sigmf(v.x), v.y * sigmf(v.y),
                       v.z * sigmf(v.z), v.w * sigmf(v.w));
}

// ---------------- NCHW -> NHWC transpose of spatial feats -------------------
__global__ __launch_bounds__(256) void k_transpose(const float* __restrict__ in) {
    __shared__ float t[64 * 33];
    const int blk   = blockIdx.x;
    const int b     = blk / (HWSZ / 32);
    const int pbase = (blk - b * (HWSZ / 32)) * 32;
    const float* inb = in + (size_t)b * CH * HWSZ;
    for (int i = threadIdx.x; i < 2048; i += 256) {
        int c = i >> 5, p = i & 31;
        t[c * 33 + p] = inb[c * HWSZ + pbase + p];
    }
    __syncthreads();
    float* outb = g_spat + ((size_t)b * HWSZ + pbase) * CH;
    for (int i = threadIdx.x; i < 2048; i += 256) {
        int p = i >> 6, c = i & 63;
        outb[p * CH + c] = t[c * 33 + p];
    }
}

// ---------------- range_proj + fixup-semantic GEMM --------------------------
// 64 px/block, thread = 4 px x 4 channels, grid 392.
__global__ __launch_bounds__(256) void k_rangeproj(
    const float* __restrict__ sem,
    const float* __restrict__ w1, const float* __restrict__ b1,
    const float* __restrict__ gg, const float* __restrict__ be,
    const float* __restrict__ w2, const float* __restrict__ b2,
    const float* __restrict__ fxw1) {
    extern __shared__ float sm[];
    float* W1t = sm;                 // [64][68]
    float* W2t = W1t + 64 * 68;      // [64][68]
    float* Wf  = W2t + 64 * 68;      // [64][68]
    float* xs  = Wf  + 64 * 68;      // [64][64] x[c][p]; later y[p][c] stride 64
    const int tid = threadIdx.x;
    for (int i = tid; i < 4096; i += 256) {
        int o = i >> 6, c = i & 63;
        W1t[c * 68 + o] = w1[i];
        W2t[c * 68 + o] = w2[i];
        Wf [c * 68 + o] = (o < NN) ? fxw1[o * 113 + 49 + c] : 0.f;
    }
    const int oq = tid & 15, p0 = (tid >> 4) << 2;
    const float4 rb1 = *(const float4*)(b1 + oq * 4);
    const float4 rg  = *(const float4*)(gg + oq * 4);
    const float4 rbe = *(const float4*)(be + oq * 4);
    const float4 rb2 = *(const float4*)(b2 + oq * 4);

    const int pg0   = blockIdx.x << 6;
    const int b     = pg0 / HWSZ;
    const int pbase = pg0 - b * HWSZ;
    const float* inb = sem + (size_t)b * CH * HWSZ + pbase;
    for (int i = tid; i < 1024; i += 256) {
        int c = i >> 4, q4 = (i & 15) << 2;
        *(float4*)(xs + c * 64 + q4) = *(const float4*)(inb + c * HWSZ + q4);
    }
    __syncthreads();

    float4 A[4];
    // fixup-semantic GEMM first
#pragma unroll
    for (int j = 0; j < 4; j++) A[j] = make_float4(0.f, 0.f, 0.f, 0.f);
#pragma unroll 8
    for (int c = 0; c < 64; c++) {
        float4 wv = *(const float4*)(Wf + c * 68 + (oq << 2));
        float4 xv = *(const float4*)(xs + (c << 6) + p0);
        FMA4W(A[0], wv, xv.x) FMA4W(A[1], wv, xv.y)
        FMA4W(A[2], wv, xv.z) FMA4W(A[3], wv, xv.w)
    }
    {
        float* fo = g_fxs + (size_t)(pg0 + p0) * CH + (oq << 2);
#pragma unroll
        for (int j = 0; j < 4; j++) *(float4*)(fo + j * CH) = A[j];
    }

    // conv1
#pragma unroll
    for (int j = 0; j < 4; j++) A[j] = rb1;
#pragma unroll 8
    for (int c = 0; c < 64; c++) {
        float4 wv = *(const float4*)(W1t + c * 68 + (oq << 2));
        float4 xv = *(const float4*)(xs  + (c << 6) + p0);
        FMA4W(A[0], wv, xv.x) FMA4W(A[1], wv, xv.y)
        FMA4W(A[2], wv, xv.z) FMA4W(A[3], wv, xv.w)
    }
#pragma unroll
    for (int j = 0; j < 4; j++) A[j] = silu4(ln_apply(A[j], rg, rbe, 1.f / 64.f));
    __syncthreads();              // all xs reads complete
#pragma unroll
    for (int j = 0; j < 4; j++)
        *(float4*)(xs + (p0 + j) * 64 + (oq << 2)) = A[j];
    __syncwarp();                 // y rows are 16-lane-group private

    // conv2
    float4 Z[4];
#pragma unroll
    for (int j = 0; j < 4; j++) Z[j] = rb2;
#pragma unroll 8
    for (int c = 0; c < 64; c++) {
        float4 wv = *(const float4*)(W2t + c * 68 + (oq << 2));
#pragma unroll
        for (int j = 0; j < 4; j++) {
            float xv = xs[(p0 + j) * 64 + c];
            FMA4W(Z[j], wv, xv)
        }
    }
    {
        float* po = g_px + (size_t)(pg0 + p0) * CH + (oq << 2);
#pragma unroll
        for (int j = 0; j < 4; j++) *(float4*)(po + j * CH) = Z[j];
    }
}

// ---------------- k_weights: raw bilateral weights -> g_comb ----------------
__global__ __launch_bounds__(256) void k_weights(const float* __restrict__ sigp) {
    __shared__ float combw[8][56];
    const int tid = threadIdx.x;
    const int wid = tid >> 5, lane = tid & 31;
    const int half = lane >> 4, q = lane & 15;
    const float sigma   = *sigp;
    const float inv2sig = 0.5f / (sigma * sigma);
    float* cw = combw[wid];
    if (lane < 3) cw[NN + lane] = 0.f;   // zero the 52-pad tail once

    const int pg = (blockIdx.x << 3) + wid;
    const int b  = pg / HWSZ;
    const int hw = pg - b * HWSZ;
    const int h  = hw / WW, w = hw - h * WW;
    const size_t bbase = (size_t)b * HWSZ;

    const float4 cv4 = ((const float4*)(g_px + (size_t)pg * CH))[q];

    for (int k = 0; k < 25; k++) {
        const int n  = (k << 1) + half;
        const int n7 = n / 7;
        const int dy = n7 - RAD, dx = n - n7 * 7 - RAD;
        const int hh = h + dy, ww2 = w + dx;
        const bool val = (n < NN) && ((unsigned)hh < (unsigned)HH) &&
                         ((unsigned)ww2 < (unsigned)WW);
        float d = 0.f;
        if (val) {
            float4 nv = ((const float4*)(g_px + (bbase + hh * WW + ww2) * CH))[q];
            float e0 = nv.x - cv4.x, e1 = nv.y - cv4.y;
            float e2 = nv.z - cv4.z, e3 = nv.w - cv4.w;
            d = fmaf(e0, e0, fmaf(e1, e1, fmaf(e2, e2, e3 * e3)));
        }
        d = grp16_sum(d);
        if (q == 0 && n < NN) {
            float d2s = (float)(dy * dy + dx * dx);
            cw[n] = val ? __expf(-fmaf(d, 1.f / 128.f, d2s * inv2sig)) : 0.f;
        }
    }
    __syncwarp();
    if (lane < 13)
        *(float4*)(g_comb + (size_t)pg * NPAD + (lane << 2)) =
            *(const float4*)(cw + (lane << 2));
}

// ---------------- k_fixup: batched fixup MLP + gate + normalize -------------
// 32 px/block, thread = 2 px x 4 outs, grid 784 (high TLP).
__global__ __launch_bounds__(256) void k_fixup(
    const float* __restrict__ fxw1, const float* __restrict__ fxb1,
    const float* __restrict__ fxg,  const float* __restrict__ fxbe,
    const float* __restrict__ fxw2, const float* __restrict__ fxb2) {
    extern __shared__ float sm[];
    float* W1t = sm;              // [49][68]
    float* W2t = W1t + 49 * 68;   // [49][68]
    float* xsh = W2t + 49 * 68;   // [32][52]
    float* ysh = xsh + 32 * NPAD; // [32][52]
    float* sb1 = ysh + 32 * NPAD;
    float* sg  = sb1 + 64;
    float* sbe = sg  + 64;
    float* sb2 = sbe + 64;
    const int tid = threadIdx.x;
    for (int i = tid; i < 49 * 64; i += 256) {
        int n = i >> 6, o = i & 63;
        W1t[n * 68 + o] = (o < NN) ? fxw1[o * 113 + n] : 0.f;
        W2t[n * 68 + o] = (o < NN) ? fxw2[o * NN + n]  : 0.f;
    }
    if (tid < 64) {
        sb1[tid] = (tid < NN) ? fxb1[tid] : 0.f;
        sg [tid] = (tid < NN) ? fxg [tid] : 0.f;
        sbe[tid] = (tid < NN) ? fxbe[tid] : 0.f;
        sb2[tid] = (tid < NN) ? fxb2[tid] : 0.f;
    }
    const int pg0 = blockIdx.x << 5;
    const float* cin = g_comb + (size_t)pg0 * NPAD;
    for (int i = tid; i < 32 * 13; i += 256) {
        int p = i / 13, j4 = (i - p * 13) << 2;
        *(float4*)(xsh + p * NPAD + j4) = *(const float4*)(cin + p * NPAD + j4);
    }
    __syncthreads();

    const int oq = tid & 15, p0 = (tid >> 4) << 1;
    const float4 b1v = *(const float4*)(sb1 + (oq << 2));
    const float4 gv  = *(const float4*)(sg  + (oq << 2));
    const float4 bev = *(const float4*)(sbe + (oq << 2));
    const float4 b2v = *(const float4*)(sb2 + (oq << 2));

    float4 A[2];
    {
        const float* fxp = g_fxs + (size_t)(pg0 + p0) * CH + (oq << 2);
#pragma unroll
        for (int j = 0; j < 2; j++) {
            float4 F = *(const float4*)(fxp + j * CH);
            A[j] = make_float4(b1v.x + F.x, b1v.y + F.y, b1v.z + F.z, b1v.w + F.w);
        }
    }
#pragma unroll 7
    for (int n = 0; n < NN; n++) {
        float4 wv = *(const float4*)(W1t + n * 68 + (oq << 2));
        float x0 = xsh[(p0 + 0) * NPAD + n];
        float x1 = xsh[(p0 + 1) * NPAD + n];
        FMA4W(A[0], wv, x0) FMA4W(A[1], wv, x1)
    }
#pragma unroll
    for (int j = 0; j < 2; j++) {
        A[j] = silu4(ln_apply(A[j], gv, bev, 1.f / 49.f));
        if (oq < 13) *(float4*)(ysh + (p0 + j) * NPAD + (oq << 2)) = A[j];
    }
    __syncwarp();

    float4 Z[2];
#pragma unroll
    for (int j = 0; j < 2; j++) Z[j] = b2v;
#pragma unroll 7
    for (int n = 0; n < NN; n++) {
        float4 wv = *(const float4*)(W2t + n * 68 + (oq << 2));
        float y0 = ysh[(p0 + 0) * NPAD + n];
        float y1 = ysh[(p0 + 1) * NPAD + n];
        FMA4W(Z[0], wv, y0) FMA4W(Z[1], wv, y1)
    }
#pragma unroll
    for (int j = 0; j < 2; j++) {
        float4 C = make_float4(0.f, 0.f, 0.f, 0.f);
        if (oq < 13) C = *(const float4*)(xsh + (p0 + j) * NPAD + (oq << 2));
        C.x *= 1.f + sigmf(Z[j].x); C.y *= 1.f + sigmf(Z[j].y);
        C.z *= 1.f + sigmf(Z[j].z); C.w *= 1.f + sigmf(Z[j].w);
        float inv = 1.f / (grp16_sum(C.x + C.y + C.z + C.w) + 1e-7f);
        if (oq < 13) {
            float* co = g_comb + (size_t)(pg0 + p0 + j) * NPAD + (oq << 2);
            *(float4*)(co) = make_float4(C.x * inv, C.y * inv, C.z * inv, C.w * inv);
        }
    }
}

// ---------------- k_reduce: weighted neighborhood reduction -----------------
__global__ __launch_bounds__(256) void k_reduce() {
    __shared__ float cws[8][NPAD];
    const int tid = threadIdx.x;
    const int wid = tid >> 5, lane = tid & 31;
    const int half = lane >> 4, q = lane & 15;
    float* cw = cws[wid];

    const int pg = (blockIdx.x << 3) + wid;
    const int b  = pg / HWSZ;
    const int hw = pg - b * HWSZ;
    const int h  = hw / WW, w = hw - h * WW;
    const size_t bbase = (size_t)b * HWSZ;

    if (lane < 13)
        *(float4*)(cw + (lane << 2)) =
            *(const float4*)(g_comb + (size_t)pg * NPAD + (lane << 2));
    __syncwarp();

    float a0 = 0.f, a1 = 0.f, a2 = 0.f, a3 = 0.f;
    for (int k = 0; k < 25; k++) {
        const int n  = (k << 1) + half;
        const int n7 = n / 7;
        const int dy = n7 - RAD, dx = n - n7 * 7 - RAD;
        const int hh = h + dy, ww2 = w + dx;
        const bool val = (n < NN) && ((unsigned)hh < (unsigned)HH) &&
                         ((unsigned)ww2 < (unsigned)WW);
        if (val) {
            float cn = cw[n];
            float4 sv = ((const float4*)(g_spat + (bbase + hh * WW + ww2) * CH))[q];
            a0 = fmaf(sv.x, cn, a0); a1 = fmaf(sv.y, cn, a1);
            a2 = fmaf(sv.z, cn, a2); a3 = fmaf(sv.w, cn, a3);
        }
    }
    a0 += __shfl_xor_sync(0xffffffffu, a0, 16);
    a1 += __shfl_xor_sync(0xffffffffu, a1, 16);
    a2 += __shfl_xor_sync(0xffffffffu, a2, 16);
    a3 += __shfl_xor_sync(0xffffffffu, a3, 16);
    if (half == 0)
        ((float4*)(g_mid + (size_t)pg * CH))[q] = make_float4(a0, a1, a2, a3);
}

// ---------------- output_proj: conv1x1 -> LN -> conv1x1 ---------------------
// 32 px/block, thread = 2 px x 4 channels, grid 784. g_mid NHWC -> out NCHW.
__global__ __launch_bounds__(256) void k_outproj(
    const float* __restrict__ w1, const float* __restrict__ b1,
    const float* __restrict__ gg, const float* __restrict__ be,
    const float* __restrict__ w2, const float* __restrict__ b2,
    float* __restrict__ out) {
    extern __shared__ float sm[];
    float* W1t = sm;                // [64][68]
    float* W2t = W1t + 64 * 68;     // [64][68]
    float* xsh = W2t + 64 * 68;     // [32][68] x[p][c], aliased as y after conv1
    const int tid = threadIdx.x;
    for (int i = tid; i < 4096; i += 256) {
        int o = i >> 6, c = i & 63;
        W1t[c * 68 + o] = w1[i];
        W2t[c * 68 + o] = w2[i];
    }
    const int oq = tid & 15, p0 = (tid >> 4) << 1;
    const float4 rb1 = *(const float4*)(b1 + oq * 4);
    const float4 rg  = *(const float4*)(gg + oq * 4);
    const float4 rbe = *(const float4*)(be + oq * 4);
    const float4 rb2 = *(const float4*)(b2 + oq * 4);

    const int pg0   = blockIdx.x << 5;
    const int b     = pg0 / HWSZ;
    const int pbase = pg0 - b * HWSZ;
    const float* inb = g_mid + (size_t)pg0 * CH;
    for (int i = tid; i < 512; i += 256) {
        int p = i >> 4, cq = (i & 15) << 2;
        *(float4*)(xsh + p * 68 + cq) = *(const float4*)(inb + p * CH + cq);
    }
    __syncthreads();

    float4 A[2];
#pragma unroll
    for (int j = 0; j < 2; j++) A[j] = rb1;
#pragma unroll 8
    for (int c = 0; c < 64; c++) {
        float4 wv = *(const float4*)(W1t + c * 68 + (oq << 2));
        float x0 = xsh[(p0 + 0) * 68 + c];
        float x1 = xsh[(p0 + 1) * 68 + c];
        FMA4W(A[0], wv, x0) FMA4W(A[1], wv, x1)
    }
#pragma unroll
    for (int j = 0; j < 2; j++) A[j] = ln_apply(A[j], rg, rbe, 1.f / 64.f);
    __syncwarp();   // conv1 reads of this group's rows done (rows group-private)
#pragma unroll
    for (int j = 0; j < 2; j++)
        *(float4*)(xsh + (p0 + j) * 68 + (oq << 2)) = A[j];
    __syncwarp();

    float4 Z[2];
#pragma unroll
    for (int j = 0; j < 2; j++) Z[j] = rb2;
#pragma unroll 8
    for (int c = 0; c < 64; c++) {
        float4 wv = *(const float4*)(W2t + c * 68 + (oq << 2));
        float x0 = xsh[(p0 + 0) * 68 + c];
        float x1 = xsh[(p0 + 1) * 68 + c];
        FMA4W(Z[0], wv, x0) FMA4W(Z[1], wv, x1)
    }
    // NCHW store: per channel, float2 across the 2 pixels
    float* outb = out + (size_t)b * CH * HWSZ + (size_t)(oq * 4) * HWSZ + pbase + p0;
    *(float2*)(outb)            = make_float2(Z[0].x, Z[1].x);
    *(float2*)(outb + HWSZ)     = make_float2(Z[0].y, Z[1].y);
    *(float2*)(outb + 2 * HWSZ) = make_float2(Z[0].z, Z[1].z);
    *(float2*)(outb + 3 * HWSZ) = make_float2(Z[0].w, Z[1].w);
}

// ---------------- launch ----------------------------------------------------
extern "C" void kernel_launch(void* const* d_in, const int* in_sizes, int n_in,
                              void* d_out, int out_size) {
    (void)in_sizes; (void)n_in; (void)out_size;
    const float* spatial  = (const float*)d_in[0];
    const float* semantic = (const float*)d_in[1];
    const float* rp_w1 = (const float*)d_in[2];
    const float* rp_b1 = (const float*)d_in[3];
    const float* rp_g  = (const float*)d_in[4];
    const float* rp_be = (const float*)d_in[5];
    const float* rp_w2 = (const float*)d_in[6];
    const float* rp_b2 = (const float*)d_in[7];
    const float* fx_w1 = (const float*)d_in[8];
    const float* fx_b1 = (const float*)d_in[9];
    const float* fx_g  = (const float*)d_in[10];
    const float* fx_be = (const float*)d_in[11];
    const float* fx_w2 = (const float*)d_in[12];
    const float* fx_b2 = (const float*)d_in[13];
    const float* op_w1 = (const float*)d_in[14];
    const float* op_b1 = (const float*)d_in[15];
    const float* op_g  = (const float*)d_in[16];
    const float* op_be = (const float*)d_in[17];
    const float* op_w2 = (const float*)d_in[18];
    const float* op_b2 = (const float*)d_in[19];
    const float* sigma = (const float*)d_in[20];
    float* out = (float*)d_out;

    const int SMEM_RP = (3 * 64 * 68 + 64 * 64) * 4;                  // 68608 B
    const int SMEM_FX = (2 * 49 * 68 + 2 * 32 * NPAD + 4 * 64) * 4;   // 41024 B
    const int SMEM_OP = (2 * 64 * 68 + 32 * 68) * 4;                  // 43520 B
    cudaFuncSetAttribute(k_rangeproj, cudaFuncAttributeMaxDynamicSharedMemorySize, SMEM_RP);
    cudaFuncSetAttribute(k_fixup,     cudaFuncAttributeMaxDynamicSharedMemorySize, SMEM_FX);
    cudaFuncSetAttribute(k_outproj,   cudaFuncAttributeMaxDynamicSharedMemorySize, SMEM_OP);

    k_transpose<<<BATCH * (HWSZ / 32), 256>>>(spatial);
    k_rangeproj<<<NPIX / 64, 256, SMEM_RP>>>(semantic, rp_w1, rp_b1, rp_g, rp_be,
                                             rp_w2, rp_b2, fx_w1);
    k_weights<<<NPIX / 8, 256>>>(sigma);
    k_fixup<<<NPIX / 32, 256, SMEM_FX>>>(fx_w1, fx_b1, fx_g, fx_be, fx_w2, fx_b2);
    k_reduce<<<NPIX / 8, 256>>>();
    k_outproj<<<NPIX / 32, 256, SMEM_OP>>>(op_w1, op_b1, op_g, op_be,
                                           op_w2, op_b2, out);
}

// round 9
// speedup vs baseline: 1.8220x; 1.8220x over previous
#include <cuda_runtime.h>
#include <math.h>

#define BATCH 2
#define CH    64
#define HH    112
#define WW    112
#define HWSZ  (HH*WW)
#define NPIX  (BATCH*HWSZ)
#define RAD   3
#define NN    49
#define NPAD  52

__device__ __align__(256) float g_px  [NPIX*CH];    // range-projected, NHWC
__device__ __align__(256) float g_spat[NPIX*CH];    // spatial feats, NHWC
__device__ __align__(256) float g_mid [NPIX*CH];    // pre-output_proj, NHWC
__device__ __align__(256) float g_fxs [NPIX*CH];    // fixup semantic partial (64-pad)
__device__ __align__(256) float g_comb[NPIX*NPAD];  // bilateral weights (52-pad)

// pre-transposed, padded weight matrices (filled by k_prep each launch)
__device__ __align__(256) float gWrp1[64*68];   // [c][o]  rp conv1
__device__ __align__(256) float gWrp2[64*68];   // [c][o]  rp conv2
__device__ __align__(256) float gWfse[64*68];   // [c][o]  fixup semantic half
__device__ __align__(256) float gWfx1[49*68];   // [n][o]  fixup conv1 (comb half)
__device__ __align__(256) float gWfx2[49*68];   // [n][o]  fixup conv2
__device__ __align__(256) float gWop1[64*68];   // [c][o]  out conv1
__device__ __align__(256) float gWop2[64*68];   // [c][o]  out conv2

__device__ __forceinline__ float grp16_sum(float v) {
#pragma unroll
    for (int off = 8; off > 0; off >>= 1)
        v += __shfl_xor_sync(0xffffffffu, v, off);
    return v;
}
__device__ __forceinline__ float sigmf(float x) {
    return 1.f / (1.f + __expf(-x));
}

#define FMA4W(Acc, W, X) { \
    Acc.x = fmaf(W.x, X, Acc.x); Acc.y = fmaf(W.y, X, Acc.y); \
    Acc.z = fmaf(W.z, X, Acc.z); Acc.w = fmaf(W.w, X, Acc.w); }

__device__ __forceinline__ float4 ln_apply(float4 A, float4 g, float4 be, float invn) {
    float s1 = grp16_sum(A.x + A.y + A.z + A.w);
    float s2 = grp16_sum(A.x*A.x + A.y*A.y + A.z*A.z + A.w*A.w);
    float u  = s1 * invn;
    float rs = rsqrtf(fmaxf(s2 * invn - u * u, 0.f) + 1e-6f);
    return make_float4(fmaf(g.x, (A.x - u) * rs, be.x),
                       fmaf(g.y, (A.y - u) * rs, be.y),
                       fmaf(g.z, (A.z - u) * rs, be.z),
                       fmaf(g.w, (A.w - u) * rs, be.w));
}
__device__ __forceinline__ float4 silu4(float4 v) {
    return make_float4(v.x * sigmf(v.x), v.y * sigmf(v.y),
                       v.z * sigmf(v.z), v.w * sigmf(v.w));
}

// ---------------- k_prep: transpose/pad all weights once --------------------
// 7 segments of 17 blocks each (17*256 = 4352 = 64*68 threads per segment).
__global__ __launch_bounds__(256) void k_prep(
    const float* __restrict__ rp_w1, const float* __restrict__ rp_w2,
    const float* __restrict__ fx_w1, const float* __restrict__ fx_w2,
    const float* __restrict__ op_w1, const float* __restrict__ op_w2) {
    const int seg = blockIdx.x / 17;
    const int idx = (blockIdx.x - seg * 17) * 256 + threadIdx.x;  // < 4352
    const int row = idx / 68, o = idx - row * 68;                  // row<64, o<68
    switch (seg) {
    case 0: gWrp1[idx] = (o < 64) ? rp_w1[o * 64 + row] : 0.f; break;
    case 1: gWrp2[idx] = (o < 64) ? rp_w2[o * 64 + row] : 0.f; break;
    case 2: gWfse[idx] = (o < NN) ? fx_w1[o * 113 + 49 + row] : 0.f; break;
    case 3: if (idx < 49 * 68) gWfx1[idx] = (o < NN) ? fx_w1[o * 113 + row] : 0.f; break;
    case 4: if (idx < 49 * 68) gWfx2[idx] = (o < NN) ? fx_w2[o * NN + row] : 0.f; break;
    case 5: gWop1[idx] = (o < 64) ? op_w1[o * 64 + row] : 0.f; break;
    default: gWop2[idx] = (o < 64) ? op_w2[o * 64 + row] : 0.f; break;
    }
}

// ---------------- NCHW -> NHWC transpose of spatial feats -------------------
__global__ __launch_bounds__(256) void k_transpose(const float* __restrict__ in) {
    __shared__ float t[64 * 33];
    const int blk   = blockIdx.x;
    const int b     = blk / (HWSZ / 32);
    const int pbase = (blk - b * (HWSZ / 32)) * 32;
    const float* inb = in + (size_t)b * CH * HWSZ;
    for (int i = threadIdx.x; i < 2048; i += 256) {
        int c = i >> 5, p = i & 31;
        t[c * 33 + p] = inb[c * HWSZ + pbase + p];
    }
    __syncthreads();
    float* outb = g_spat + ((size_t)b * HWSZ + pbase) * CH;
    for (int i = threadIdx.x; i < 2048; i += 256) {
        int p = i >> 6, c = i & 63;
        outb[p * CH + c] = t[c * 33 + p];
    }
}

// ---------------- range_proj + fixup-semantic GEMM --------------------------
// 64 px/block, thread = 4 px x 4 channels, grid 392.
__global__ __launch_bounds__(256) void k_rangeproj(
    const float* __restrict__ sem,
    const float* __restrict__ b1,
    const float* __restrict__ gg, const float* __restrict__ be,
    const float* __restrict__ b2) {
    extern __shared__ float sm[];
    float* W1t = sm;                 // [64][68]
    float* W2t = W1t + 64 * 68;      // [64][68]
    float* Wf  = W2t + 64 * 68;      // [64][68]
    float* xs  = Wf  + 64 * 68;      // [64][64] x[c][p]; later y[p][c] stride 64
    const int tid = threadIdx.x;
    for (int i = tid; i < 1088; i += 256) {
        ((float4*)W1t)[i] = ((const float4*)gWrp1)[i];
        ((float4*)W2t)[i] = ((const float4*)gWrp2)[i];
        ((float4*)Wf )[i] = ((const float4*)gWfse)[i];
    }
    const int oq = tid & 15, p0 = (tid >> 4) << 2;
    const float4 rb1 = *(const float4*)(b1 + oq * 4);
    const float4 rg  = *(const float4*)(gg + oq * 4);
    const float4 rbe = *(const float4*)(be + oq * 4);
    const float4 rb2 = *(const float4*)(b2 + oq * 4);

    const int pg0   = blockIdx.x << 6;
    const int b     = pg0 / HWSZ;
    const int pbase = pg0 - b * HWSZ;
    const float* inb = sem + (size_t)b * CH * HWSZ + pbase;
    for (int i = tid; i < 1024; i += 256) {
        int c = i >> 4, q4 = (i & 15) << 2;
        *(float4*)(xs + c * 64 + q4) = *(const float4*)(inb + c * HWSZ + q4);
    }
    __syncthreads();

    float4 A[4];
    // fixup-semantic GEMM first
#pragma unroll
    for (int j = 0; j < 4; j++) A[j] = make_float4(0.f, 0.f, 0.f, 0.f);
#pragma unroll 8
    for (int c = 0; c < 64; c++) {
        float4 wv = *(const float4*)(Wf + c * 68 + (oq << 2));
        float4 xv = *(const float4*)(xs + (c << 6) + p0);
        FMA4W(A[0], wv, xv.x) FMA4W(A[1], wv, xv.y)
        FMA4W(A[2], wv, xv.z) FMA4W(A[3], wv, xv.w)
    }
    {
        float* fo = g_fxs + (size_t)(pg0 + p0) * CH + (oq << 2);
#pragma unroll
        for (int j = 0; j < 4; j++) *(float4*)(fo + j * CH) = A[j];
    }

    // conv1
#pragma unroll
    for (int j = 0; j < 4; j++) A[j] = rb1;
#pragma unroll 8
    for (int c = 0; c < 64; c++) {
        float4 wv = *(const float4*)(W1t + c * 68 + (oq << 2));
        float4 xv = *(const float4*)(xs  + (c << 6) + p0);
        FMA4W(A[0], wv, xv.x) FMA4W(A[1], wv, xv.y)
        FMA4W(A[2], wv, xv.z) FMA4W(A[3], wv, xv.w)
    }
#pragma unroll
    for (int j = 0; j < 4; j++) A[j] = silu4(ln_apply(A[j], rg, rbe, 1.f / 64.f));
    __syncthreads();              // all xs reads complete
#pragma unroll
    for (int j = 0; j < 4; j++)
        *(float4*)(xs + (p0 + j) * 64 + (oq << 2)) = A[j];
    __syncwarp();                 // y rows are 16-lane-group private

    // conv2
    float4 Z[4];
#pragma unroll
    for (int j = 0; j < 4; j++) Z[j] = rb2;
#pragma unroll 8
    for (int c = 0; c < 64; c++) {
        float4 wv = *(const float4*)(W2t + c * 68 + (oq << 2));
#pragma unroll
        for (int j = 0; j < 4; j++) {
            float xv = xs[(p0 + j) * 64 + c];
            FMA4W(Z[j], wv, xv)
        }
    }
    {
        float* po = g_px + (size_t)(pg0 + p0) * CH + (oq << 2);
#pragma unroll
        for (int j = 0; j < 4; j++) *(float4*)(po + j * CH) = Z[j];
    }
}

// ---------------- k_weights: raw bilateral weights -> g_comb ----------------
__global__ __launch_bounds__(256) void k_weights(const float* __restrict__ sigp) {
    __shared__ float combw[8][56];
    const int tid = threadIdx.x;
    const int wid = tid >> 5, lane = tid & 31;
    const int half = lane >> 4, q = lane & 15;
    const float sigma   = *sigp;
    const float inv2sig = 0.5f / (sigma * sigma);
    float* cw = combw[wid];
    if (lane < 3) cw[NN + lane] = 0.f;   // zero the 52-pad tail

    const int pg = (blockIdx.x << 3) + wid;
    const int b  = pg / HWSZ;
    const int hw = pg - b * HWSZ;
    const int h  = hw / WW, w = hw - h * WW;
    const size_t bbase = (size_t)b * HWSZ;

    const float4 cv4 = ((const float4*)(g_px + (size_t)pg * CH))[q];

    for (int k = 0; k < 25; k++) {
        const int n  = (k << 1) + half;
        const int n7 = n / 7;
        const int dy = n7 - RAD, dx = n - n7 * 7 - RAD;
        const int hh = h + dy, ww2 = w + dx;
        const bool val = (n < NN) && ((unsigned)hh < (unsigned)HH) &&
                         ((unsigned)ww2 < (unsigned)WW);
        float d = 0.f;
        if (val) {
            float4 nv = ((const float4*)(g_px + (bbase + hh * WW + ww2) * CH))[q];
            float e0 = nv.x - cv4.x, e1 = nv.y - cv4.y;
            float e2 = nv.z - cv4.z, e3 = nv.w - cv4.w;
            d = fmaf(e0, e0, fmaf(e1, e1, fmaf(e2, e2, e3 * e3)));
        }
        d = grp16_sum(d);
        if (q == 0 && n < NN) {
            float d2s = (float)(dy * dy + dx * dx);
            cw[n] = val ? __expf(-fmaf(d, 1.f / 128.f, d2s * inv2sig)) : 0.f;
        }
    }
    __syncwarp();
    if (lane < 13)
        *(float4*)(g_comb + (size_t)pg * NPAD + (lane << 2)) =
            *(const float4*)(cw + (lane << 2));
}

// ---------------- k_fixup: batched fixup MLP + gate + normalize -------------
// 64 px/block, thread = 4 px x 4 outs, grid 392 (R5 config, cheap prologue).
__global__ __launch_bounds__(256) void k_fixup(
    const float* __restrict__ fxb1,
    const float* __restrict__ fxg,  const float* __restrict__ fxbe,
    const float* __restrict__ fxb2) {
    extern __shared__ float sm[];
    float* W1t = sm;              // [49][68]
    float* W2t = W1t + 49 * 68;   // [49][68]
    float* xsh = W2t + 49 * 68;   // [64][52]
    float* ysh = xsh + 64 * NPAD; // [64][52]
    float* sb1 = ysh + 64 * NPAD;
    float* sg  = sb1 + 64;
    float* sbe = sg  + 64;
    float* sb2 = sbe + 64;
    const int tid = threadIdx.x;
    for (int i = tid; i < 833; i += 256) {        // 49*68/4 = 833
        ((float4*)W1t)[i] = ((const float4*)gWfx1)[i];
        ((float4*)W2t)[i] = ((const float4*)gWfx2)[i];
    }
    if (tid < 64) {
        sb1[tid] = (tid < NN) ? fxb1[tid] : 0.f;
        sg [tid] = (tid < NN) ? fxg [tid] : 0.f;
        sbe[tid] = (tid < NN) ? fxbe[tid] : 0.f;
        sb2[tid] = (tid < NN) ? fxb2[tid] : 0.f;
    }
    const int pg0 = blockIdx.x << 6;
    const float* cin = g_comb + (size_t)pg0 * NPAD;
    for (int i = tid; i < 64 * 13; i += 256) {
        int p = i / 13, j4 = (i - p * 13) << 2;
        *(float4*)(xsh + p * NPAD + j4) = *(const float4*)(cin + p * NPAD + j4);
    }
    __syncthreads();

    const int oq = tid & 15, p0 = (tid >> 4) << 2;
    const float4 b1v = *(const float4*)(sb1 + (oq << 2));
    const float4 gv  = *(const float4*)(sg  + (oq << 2));
    const float4 bev = *(const float4*)(sbe + (oq << 2));
    const float4 b2v = *(const float4*)(sb2 + (oq << 2));

    float4 A[4];
    {
        const float* fxp = g_fxs + (size_t)(pg0 + p0) * CH + (oq << 2);
#pragma unroll
        for (int j = 0; j < 4; j++) {
            float4 F = *(const float4*)(fxp + j * CH);
            A[j] = make_float4(b1v.x + F.x, b1v.y + F.y, b1v.z + F.z, b1v.w + F.w);
        }
    }
#pragma unroll 7
    for (int n = 0; n < NN; n++) {
        float4 wv = *(const float4*)(W1t + n * 68 + (oq << 2));
#pragma unroll
        for (int j = 0; j < 4; j++) {
            float xv = xsh[(p0 + j) * NPAD + n];
            FMA4W(A[j], wv, xv)
        }
    }
#pragma unroll
    for (int j = 0; j < 4; j++) {
        A[j] = silu4(ln_apply(A[j], gv, bev, 1.f / 49.f));
        if (oq < 13) *(float4*)(ysh + (p0 + j) * NPAD + (oq << 2)) = A[j];
    }
    __syncwarp();

    float4 Z[4];
#pragma unroll
    for (int j = 0; j < 4; j++) Z[j] = b2v;
#pragma unroll 7
    for (int n = 0; n < NN; n++) {
        float4 wv = *(const float4*)(W2t + n * 68 + (oq << 2));
#pragma unroll
        for (int j = 0; j < 4; j++) {
            float yv = ysh[(p0 + j) * NPAD + n];
            FMA4W(Z[j], wv, yv)
        }
    }
#pragma unroll
    for (int j = 0; j < 4; j++) {
        float4 C = make_float4(0.f, 0.f, 0.f, 0.f);
        if (oq < 13) C = *(const float4*)(xsh + (p0 + j) * NPAD + (oq << 2));
        C.x *= 1.f + sigmf(Z[j].x); C.y *= 1.f + sigmf(Z[j].y);
        C.z *= 1.f + sigmf(Z[j].z); C.w *= 1.f + sigmf(Z[j].w);
        float inv = 1.f / (grp16_sum(C.x + C.y + C.z + C.w) + 1e-7f);
        if (oq < 13) {
            float* co = g_comb + (size_t)(pg0 + p0 + j) * NPAD + (oq << 2);
            *(float4*)(co) = make_float4(C.x * inv, C.y * inv, C.z * inv, C.w * inv);
        }
    }
}

// ---------------- k_reduce: weighted neighborhood reduction -----------------
__global__ __launch_bounds__(256) void k_reduce() {
    __shared__ float cws[8][NPAD];
    const int tid = threadIdx.x;
    const int wid = tid >> 5, lane = tid & 31;
    const int half = lane >> 4, q = lane & 15;
    float* cw = cws[wid];

    const int pg = (blockIdx.x << 3) + wid;
    const int b  = pg / HWSZ;
    const int hw = pg - b * HWSZ;
    const int h  = hw / WW, w = hw - h * WW;
    const size_t bbase = (size_t)b * HWSZ;

    if (lane < 13)
        *(float4*)(cw + (lane << 2)) =
            *(const float4*)(g_comb + (size_t)pg * NPAD + (lane << 2));
    __syncwarp();

    float a0 = 0.f, a1 = 0.f, a2 = 0.f, a3 = 0.f;
    for (int k = 0; k < 25; k++) {
        const int n  = (k << 1) + half;
        const int n7 = n / 7;
        const int dy = n7 - RAD, dx = n - n7 * 7 - RAD;
        const int hh = h + dy, ww2 = w + dx;
        const bool val = (n < NN) && ((unsigned)hh < (unsigned)HH) &&
                         ((unsigned)ww2 < (unsigned)WW);
        if (val) {
            float cn = cw[n];
            float4 sv = ((const float4*)(g_spat + (bbase + hh * WW + ww2) * CH))[q];
            a0 = fmaf(sv.x, cn, a0); a1 = fmaf(sv.y, cn, a1);
            a2 = fmaf(sv.z, cn, a2); a3 = fmaf(sv.w, cn, a3);
        }
    }
    a0 += __shfl_xor_sync(0xffffffffu, a0, 16);
    a1 += __shfl_xor_sync(0xffffffffu, a1, 16);
    a2 += __shfl_xor_sync(0xffffffffu, a2, 16);
    a3 += __shfl_xor_sync(0xffffffffu, a3, 16);
    if (half == 0)
        ((float4*)(g_mid + (size_t)pg * CH))[q] = make_float4(a0, a1, a2, a3);
}

// ---------------- output_proj: conv1x1 -> LN -> conv1x1 ---------------------
// 64 px/block, thread = 4 px x 4 channels, grid 392. g_mid NHWC -> out NCHW.
__global__ __launch_bounds__(256) void k_outproj(
    const float* __restrict__ b1,
    const float* __restrict__ gg, const float* __restrict__ be,
    const float* __restrict__ b2,
    float* __restrict__ out) {
    extern __shared__ float sm[];
    float* W1t = sm;                // [64][68]
    float* W2t = W1t + 64 * 68;     // [64][68]
    float* xsh = W2t + 64 * 68;     // [64][68] x[p][c], aliased as y after conv1
    const int tid = threadIdx.x;
    for (int i = tid; i < 1088; i += 256) {
        ((float4*)W1t)[i] = ((const float4*)gWop1)[i];
        ((float4*)W2t)[i] = ((const float4*)gWop2)[i];
    }
    const int oq = tid & 15, p0 = (tid >> 4) << 2;
    const float4 rb1 = *(const float4*)(b1 + oq * 4);
    const float4 rg  = *(const float4*)(gg + oq * 4);
    const float4 rbe = *(const float4*)(be + oq * 4);
    const float4 rb2 = *(const float4*)(b2 + oq * 4);

    const int pg0   = blockIdx.x << 6;
    const int b     = pg0 / HWSZ;
    const int pbase = pg0 - b * HWSZ;
    const float* inb = g_mid + (size_t)pg0 * CH;
    for (int i = tid; i < 1024; i += 256) {
        int p = i >> 4, cq = (i & 15) << 2;
        *(float4*)(xsh + p * 68 + cq) = *(const float4*)(inb + p * CH + cq);
    }
    __syncthreads();

    float4 A[4];
#pragma unroll
    for (int j = 0; j < 4; j++) A[j] = rb1;
#pragma unroll 8
    for (int c = 0; c < 64; c++) {
        float4 wv = *(const float4*)(W1t + c * 68 + (oq << 2));
#pragma unroll
        for (int j = 0; j < 4; j++) {
            float xv = xsh[(p0 + j) * 68 + c];
            FMA4W(A[j], wv, xv)
        }
    }
#pragma unroll
    for (int j = 0; j < 4; j++) A[j] = ln_apply(A[j], rg, rbe, 1.f / 64.f);
    __syncwarp();   // conv1 reads of this group's rows done (rows group-private)
#pragma unroll
    for (int j = 0; j < 4; j++)
        *(float4*)(xsh + (p0 + j) * 68 + (oq << 2)) = A[j];
    __syncwarp();

    float4 Z[4];
#pragma unroll
    for (int j = 0; j < 4; j++) Z[j] = rb2;
#pragma unroll 8
    for (int c = 0; c < 64; c++) {
        float4 wv = *(const float4*)(W2t + c * 68 + (oq << 2));
#pragma unroll
        for (int j = 0; j < 4; j++) {
            float xv = xsh[(p0 + j) * 68 + c];
            FMA4W(Z[j], wv, xv)
        }
    }
    float* outb = out + (size_t)b * CH * HWSZ + (size_t)(oq * 4) * HWSZ + pbase + p0;
    *(float4*)(outb)            = make_float4(Z[0].x, Z[1].x, Z[2].x, Z[3].x);
    *(float4*)(outb + HWSZ)     = make_float4(Z[0].y, Z[1].y, Z[2].y, Z[3].y);
    *(float4*)(outb + 2 * HWSZ) = make_float4(Z[0].z, Z[1].z, Z[2].z, Z[3].z);
    *(float4*)(outb + 3 * HWSZ) = make_float4(Z[0].w, Z[1].w, Z[2].w, Z[3].w);
}

// ---------------- launch ----------------------------------------------------
extern "C" void kernel_launch(void* const* d_in, const int* in_sizes, int n_in,
                              void* d_out, int out_size) {
    (void)in_sizes; (void)n_in; (void)out_size;
    const float* spatial  = (const float*)d_in[0];
    const float* semantic = (const float*)d_in[1];
    const float* rp_w1 = (const float*)d_in[2];
    const float* rp_b1 = (const float*)d_in[3];
    const float* rp_g  = (const float*)d_in[4];
    const float* rp_be = (const float*)d_in[5];
    const float* rp_w2 = (const float*)d_in[6];
    const float* rp_b2 = (const float*)d_in[7];
    const float* fx_w1 = (const float*)d_in[8];
    const float* fx_b1 = (const float*)d_in[9];
    const float* fx_g  = (const float*)d_in[10];
    const float* fx_be = (const float*)d_in[11];
    const float* fx_w2 = (const float*)d_in[12];
    const float* fx_b2 = (const float*)d_in[13];
    const float* op_w1 = (const float*)d_in[14];
    const float* op_b1 = (const float*)d_in[15];
    const float* op_g  = (const float*)d_in[16];
    const float* op_be = (const float*)d_in[17];
    const float* op_w2 = (const float*)d_in[18];
    const float* op_b2 = (const float*)d_in[19];
    const float* sigma = (const float*)d_in[20];
    float* out = (float*)d_out;

    const int SMEM_RP = (3 * 64 * 68 + 64 * 64) * 4;                  // 68608 B
    const int SMEM_FX = (2 * 49 * 68 + 2 * 64 * NPAD + 4 * 64) * 4;   // 54304 B
    const int SMEM_OP = (2 * 64 * 68 + 64 * 68) * 4;                  // 52224 B
    cudaFuncSetAttribute(k_rangeproj, cudaFuncAttributeMaxDynamicSharedMemorySize, SMEM_RP);
    cudaFuncSetAttribute(k_fixup,     cudaFuncAttributeMaxDynamicSharedMemorySize, SMEM_FX);
    cudaFuncSetAttribute(k_outproj,   cudaFuncAttributeMaxDynamicSharedMemorySize, SMEM_OP);

    k_prep<<<7 * 17, 256>>>(rp_w1, rp_w2, fx_w1, fx_w2, op_w1, op_w2);
    k_transpose<<<BATCH * (HWSZ / 32), 256>>>(spatial);
    k_rangeproj<<<NPIX / 64, 256, SMEM_RP>>>(semantic, rp_b1, rp_g, rp_be, rp_b2);
    k_weights<<<NPIX / 8, 256>>>(sigma);
    k_fixup<<<NPIX / 64, 256, SMEM_FX>>>(fx_b1, fx_g, fx_be, fx_b2);
    k_reduce<<<NPIX / 8, 256>>>();
    k_outproj<<<NPIX / 64, 256, SMEM_OP>>>(op_b1, op_g, op_be, op_b2, out);
}

// round 13
// speedup vs baseline: 2.1080x; 1.1570x over previous
#include <cuda_runtime.h>
#include <math.h>

#define BATCH 2
#define CH    64
#define HH    112
#define WW    112
#define HWSZ  (HH*WW)
#define NPIX  (BATCH*HWSZ)
#define RAD   3
#define NN    49
#define NPAD  52

__device__ __align__(256) float g_px  [NPIX*CH];    // range-projected, NHWC
__device__ __align__(256) float g_spat[NPIX*CH];    // spatial feats, NHWC
__device__ __align__(256) float g_mid [NPIX*CH];    // pre-output_proj, NHWC
__device__ __align__(256) float g_fxs [NPIX*CH];    // fixup semantic partial (64-pad)
__device__ __align__(256) float g_comb[NPIX*NPAD];  // bilateral weights (52-pad)
__device__ __align__(256) float g_nrm [NPIX];       // ||px[p]||^2

// pre-transposed, padded weight matrices (filled by k_prep each launch)
__device__ __align__(256) float gWrp1[64*68];
__device__ __align__(256) float gWrp2[64*68];
__device__ __align__(256) float gWfse[64*68];
__device__ __align__(256) float gWfx1[49*68];
__device__ __align__(256) float gWfx2[49*68];
__device__ __align__(256) float gWop1[64*68];
__device__ __align__(256) float gWop2[64*68];

__device__ __forceinline__ float grp16_sum(float v) {
#pragma unroll
    for (int off = 8; off > 0; off >>= 1)
        v += __shfl_xor_sync(0xffffffffu, v, off);
    return v;
}
__device__ __forceinline__ float sigmf(float x) {
    return 1.f / (1.f + __expf(-x));
}

#define FMA4W(Acc, W, X) { \
    Acc.x = fmaf(W.x, X, Acc.x); Acc.y = fmaf(W.y, X, Acc.y); \
    Acc.z = fmaf(W.z, X, Acc.z); Acc.w = fmaf(W.w, X, Acc.w); }

__device__ __forceinline__ float4 ln_apply(float4 A, float4 g, float4 be, float invn) {
    float s1 = grp16_sum(A.x + A.y + A.z + A.w);
    float s2 = grp16_sum(A.x*A.x + A.y*A.y + A.z*A.z + A.w*A.w);
    float u  = s1 * invn;
    float rs = rsqrtf(fmaxf(s2 * invn - u * u, 0.f) + 1e-6f);
    return make_float4(fmaf(g.x, (A.x - u) * rs, be.x),
                       fmaf(g.y, (A.y - u) * rs, be.y),
                       fmaf(g.z, (A.z - u) * rs, be.z),
                       fmaf(g.w, (A.w - u) * rs, be.w));
}
__device__ __forceinline__ float4 silu4(float4 v) {
    return make_float4(v.x * sigmf(v.x), v.y * sigmf(v.y),
                       v.z * sigmf(v.z), v.w * sigmf(v.w));
}

// ---------------- k_prep: transpose/pad all weights once --------------------
__global__ __launch_bounds__(256) void k_prep(
    const float* __restrict__ rp_w1, const float* __restrict__ rp_w2,
    const float* __restrict__ fx_w1, const float* __restrict__ fx_w2,
    const float* __restrict__ op_w1, const float* __restrict__ op_w2) {
    const int seg = blockIdx.x / 17;
    const int idx = (blockIdx.x - seg * 17) * 256 + threadIdx.x;  // < 4352
    const int row = idx / 68, o = idx - row * 68;
    switch (seg) {
    case 0: gWrp1[idx] = (o < 64) ? rp_w1[o * 64 + row] : 0.f; break;
    case 1: gWrp2[idx] = (o < 64) ? rp_w2[o * 64 + row] : 0.f; break;
    case 2: gWfse[idx] = (o < NN) ? fx_w1[o * 113 + 49 + row] : 0.f; break;
    case 3: if (idx < 49 * 68) gWfx1[idx] = (o < NN) ? fx_w1[o * 113 + row] : 0.f; break;
    case 4: if (idx < 49 * 68) gWfx2[idx] = (o < NN) ? fx_w2[o * NN + row] : 0.f; break;
    case 5: gWop1[idx] = (o < 64) ? op_w1[o * 64 + row] : 0.f; break;
    default: gWop2[idx] = (o < 64) ? op_w2[o * 64 + row] : 0.f; break;
    }
}

// ---------------- NCHW -> NHWC transpose of spatial feats -------------------
__global__ __launch_bounds__(256) void k_transpose(const float* __restrict__ in) {
    __shared__ float t[64 * 33];
    const int blk   = blockIdx.x;
    const int b     = blk / (HWSZ / 32);
    const int pbase = (blk - b * (HWSZ / 32)) * 32;
    const float* inb = in + (size_t)b * CH * HWSZ;
    for (int i = threadIdx.x; i < 2048; i += 256) {
        int c = i >> 5, p = i & 31;
        t[c * 33 + p] = inb[c * HWSZ + pbase + p];
    }
    __syncthreads();
    float* outb = g_spat + ((size_t)b * HWSZ + pbase) * CH;
    for (int i = threadIdx.x; i < 2048; i += 256) {
        int p = i >> 6, c = i & 63;
        outb[p * CH + c] = t[c * 33 + p];
    }
}

// ---------------- range_proj + fixup-semantic GEMM + norms ------------------
// 64 px/block, thread = 4 px x 4 channels, grid 392.
__global__ __launch_bounds__(256) void k_rangeproj(
    const float* __restrict__ sem,
    const float* __restrict__ b1,
    const float* __restrict__ gg, const float* __restrict__ be,
    const float* __restrict__ b2) {
    extern __shared__ float sm[];
    float* W1t = sm;                 // [64][68]
    float* W2t = W1t + 64 * 68;      // [64][68]
    float* Wf  = W2t + 64 * 68;      // [64][68]
    float* xs  = Wf  + 64 * 68;      // [64][64] x[c][p]; later y[p][c] stride 64
    const int tid = threadIdx.x;
    for (int i = tid; i < 1088; i += 256) {
        ((float4*)W1t)[i] = ((const float4*)gWrp1)[i];
        ((float4*)W2t)[i] = ((const float4*)gWrp2)[i];
        ((float4*)Wf )[i] = ((const float4*)gWfse)[i];
    }
    const int oq = tid & 15, p0 = (tid >> 4) << 2;
    const float4 rb1 = *(const float4*)(b1 + oq * 4);
    const float4 rg  = *(const float4*)(gg + oq * 4);
    const float4 rbe = *(const float4*)(be + oq * 4);
    const float4 rb2 = *(const float4*)(b2 + oq * 4);

    const int pg0   = blockIdx.x << 6;
    const int b     = pg0 / HWSZ;
    const int pbase = pg0 - b * HWSZ;
    const float* inb = sem + (size_t)b * CH * HWSZ + pbase;
    for (int i = tid; i < 1024; i += 256) {
        int c = i >> 4, q4 = (i & 15) << 2;
        *(float4*)(xs + c * 64 + q4) = *(const float4*)(inb + c * HWSZ + q4);
    }
    __syncthreads();

    float4 A[4];
    // fixup-semantic GEMM first
#pragma unroll
    for (int j = 0; j < 4; j++) A[j] = make_float4(0.f, 0.f, 0.f, 0.f);
#pragma unroll 8
    for (int c = 0; c < 64; c++) {
        float4 wv = *(const float4*)(Wf + c * 68 + (oq << 2));
        float4 xv = *(const float4*)(xs + (c << 6) + p0);
        FMA4W(A[0], wv, xv.x) FMA4W(A[1], wv, xv.y)
        FMA4W(A[2], wv, xv.z) FMA4W(A[3], wv, xv.w)
    }
    {
        float* fo = g_fxs + (size_t)(pg0 + p0) * CH + (oq << 2);
#pragma unroll
        for (int j = 0; j < 4; j++) *(float4*)(fo + j * CH) = A[j];
    }

    // conv1
#pragma unroll
    for (int j = 0; j < 4; j++) A[j] = rb1;
#pragma unroll 8
    for (int c = 0; c < 64; c++) {
        float4 wv = *(const float4*)(W1t + c * 68 + (oq << 2));
        float4 xv = *(const float4*)(xs  + (c << 6) + p0);
        FMA4W(A[0], wv, xv.x) FMA4W(A[1], wv, xv.y)
        FMA4W(A[2], wv, xv.z) FMA4W(A[3], wv, xv.w)
    }
#pragma unroll
    for (int j = 0; j < 4; j++) A[j] = silu4(ln_apply(A[j], rg, rbe, 1.f / 64.f));
    __syncthreads();              // all xs reads complete
#pragma unroll
    for (int j = 0; j < 4; j++)
        *(float4*)(xs + (p0 + j) * 64 + (oq << 2)) = A[j];
    __syncwarp();                 // y rows are 16-lane-group private

    // conv2
    float4 Z[4];
#pragma unroll
    for (int j = 0; j < 4; j++) Z[j] = rb2;
#pragma unroll 8
    for (int c = 0; c < 64; c++) {
        float4 wv = *(const float4*)(W2t + c * 68 + (oq << 2));
#pragma unroll
        for (int j = 0; j < 4; j++) {
            float xv = xs[(p0 + j) * 64 + c];
            FMA4W(Z[j], wv, xv)
        }
    }
    {
        float* po = g_px + (size_t)(pg0 + p0) * CH + (oq << 2);
#pragma unroll
        for (int j = 0; j < 4; j++) *(float4*)(po + j * CH) = Z[j];
    }
    // norms: ||px[p]||^2 for the bilateral dot-product form
#pragma unroll
    for (int j = 0; j < 4; j++) {
        float s = grp16_sum(Z[j].x*Z[j].x + Z[j].y*Z[j].y +
                            Z[j].z*Z[j].z + Z[j].w*Z[j].w);
        if (oq == 0) g_nrm[pg0 + p0 + j] = s;
    }
}

// ---------------- k_weights: raw bilateral weights -> g_comb ----------------
// warp/pixel; 8-lane group per neighbor, 4 neighbors/iteration, smem table.
__global__ __launch_bounds__(256) void k_weights(const float* __restrict__ sigp) {
    __shared__ int4  tbl[52];       // {byteOff, dy, dx, bits(d2s*inv2sig)}
    __shared__ float cws[8][56];
    const int tid = threadIdx.x;
    if (tid < 52) {
        const int n  = tid;
        const int n7 = n / 7;
        const int dy = (n < NN) ? n7 - RAD : 1000;   // n>=49 -> never valid
        const int dx = n - n7 * 7 - RAD;
        const int offB = (dy * WW + dx) * (CH * 4);
        const float sigma = *sigp;
        const float d2sw = (float)(dy * dy + dx * dx) * (0.5f / (sigma * sigma));
        tbl[n] = make_int4(offB, dy, dx, __float_as_int(d2sw));
    }
    __syncthreads();

    const int wid = tid >> 5, lane = tid & 31;
    const int g = lane >> 3, r = lane & 7;
    float* cw = cws[wid];

    const int pg = (blockIdx.x << 3) + wid;
    const int b  = pg / HWSZ;
    const int hw = pg - b * HWSZ;
    const int h  = hw / WW, w = hw - h * WW;

    const char* rowp = (const char*)(g_px + (size_t)pg * CH) + r * 32;
    const float4 cv0 = *(const float4*)(rowp);
    const float4 cv1 = *(const float4*)(rowp + 16);
    const float  cb  = -g_nrm[pg] * (1.f / 128.f);   // -Sc/128

#pragma unroll
    for (int t = 0; t < 13; t++) {
        const int n = (t << 2) + g;
        const int4 e = tbl[n];
        const int hh = h + e.y, ww2 = w + e.z;
        const bool valid = ((unsigned)hh < (unsigned)HH) &&
                           ((unsigned)ww2 < (unsigned)WW);
        float d = 0.f;
        if (valid) {
            const float4 nv0 = *(const float4*)(rowp + e.x);
            const float4 nv1 = *(const float4*)(rowp + e.x + 16);
            d = cv0.x * nv0.x;
            d = fmaf(cv0.y, nv0.y, d); d = fmaf(cv0.z, nv0.z, d);
            d = fmaf(cv0.w, nv0.w, d); d = fmaf(cv1.x, nv1.x, d);
            d = fmaf(cv1.y, nv1.y, d); d = fmaf(cv1.z, nv1.z, d);
            d = fmaf(cv1.w, nv1.w, d);
        }
        d += __shfl_xor_sync(0xffffffffu, d, 4);
        d += __shfl_xor_sync(0xffffffffu, d, 2);
        d += __shfl_xor_sync(0xffffffffu, d, 1);
        if (r == 0) {
            float res = 0.f;
            if (valid) {
                const float Sn = g_nrm[pg + (e.x >> 8)];   // offB/256 = dy*WW+dx
                // -max(dist2,0)/128 = min((2d - Sn - Sc)/128, 0)
                float arg = fminf(fmaf(d, 1.f / 64.f,
                                       fmaf(Sn, -1.f / 128.f, cb)), 0.f)
                          - __int_as_float(e.w);
                res = __expf(arg);
            }
            cw[n] = res;
        }
    }
    __syncwarp();
    if (lane < 13)
        *(float4*)(g_comb + (size_t)pg * NPAD + (lane << 2)) =
            *(const float4*)(cw + (lane << 2));
}

// ---------------- k_fixup: batched fixup MLP + gate + normalize -------------
// 64 px/block, thread = 4 px x 4 outs, grid 392.
__global__ __launch_bounds__(256) void k_fixup(
    const float* __restrict__ fxb1,
    const float* __restrict__ fxg,  const float* __restrict__ fxbe,
    const float* __restrict__ fxb2) {
    extern __shared__ float sm[];
    float* W1t = sm;              // [49][68]
    float* W2t = W1t + 49 * 68;   // [49][68]
    float* xsh = W2t + 49 * 68;   // [64][52]
    float* ysh = xsh + 64 * NPAD; // [64][52]
    float* sb1 = ysh + 64 * NPAD;
    float* sg  = sb1 + 64;
    float* sbe = sg  + 64;
    float* sb2 = sbe + 64;
    const int tid = threadIdx.x;
    for (int i = tid; i < 833; i += 256) {
        ((float4*)W1t)[i] = ((const float4*)gWfx1)[i];
        ((float4*)W2t)[i] = ((const float4*)gWfx2)[i];
    }
    if (tid < 64) {
        sb1[tid] = (tid < NN) ? fxb1[tid] : 0.f;
        sg [tid] = (tid < NN) ? fxg [tid] : 0.f;
        sbe[tid] = (tid < NN) ? fxbe[tid] : 0.f;
        sb2[tid] = (tid < NN) ? fxb2[tid] : 0.f;
    }
    const int pg0 = blockIdx.x << 6;
    const float* cin = g_comb + (size_t)pg0 * NPAD;
    for (int i = tid; i < 64 * 13; i += 256) {
        int p = i / 13, j4 = (i - p * 13) << 2;
        *(float4*)(xsh + p * NPAD + j4) = *(const float4*)(cin + p * NPAD + j4);
    }
    __syncthreads();

    const int oq = tid & 15, p0 = (tid >> 4) << 2;
    const float4 b1v = *(const float4*)(sb1 + (oq << 2));
    const float4 gv  = *(const float4*)(sg  + (oq << 2));
    const float4 bev = *(const float4*)(sbe + (oq << 2));
    const float4 b2v = *(const float4*)(sb2 + (oq << 2));

    float4 A[4];
    {
        const float* fxp = g_fxs + (size_t)(pg0 + p0) * CH + (oq << 2);
#pragma unroll
        for (int j = 0; j < 4; j++) {
            float4 F = *(const float4*)(fxp + j * CH);
            A[j] = make_float4(b1v.x + F.x, b1v.y + F.y, b1v.z + F.z, b1v.w + F.w);
        }
    }
#pragma unroll 7
    for (int n = 0; n < NN; n++) {
        float4 wv = *(const float4*)(W1t + n * 68 + (oq << 2));
#pragma unroll
        for (int j = 0; j < 4; j++) {
            float xv = xsh[(p0 + j) * NPAD + n];
            FMA4W(A[j], wv, xv)
        }
    }
#pragma unroll
    for (int j = 0; j < 4; j++) {
        A[j] = silu4(ln_apply(A[j], gv, bev, 1.f / 49.f));
        if (oq < 13) *(float4*)(ysh + (p0 + j) * NPAD + (oq << 2)) = A[j];
    }
    __syncwarp();

    float4 Z[4];
#pragma unroll
    for (int j = 0; j < 4; j++) Z[j] = b2v;
#pragma unroll 7
    for (int n = 0; n < NN; n++) {
        float4 wv = *(const float4*)(W2t + n * 68 + (oq << 2));
#pragma unroll
        for (int j = 0; j < 4; j++) {
            float yv = ysh[(p0 + j) * NPAD + n];
            FMA4W(Z[j], wv, yv)
        }
    }
#pragma unroll
    for (int j = 0; j < 4; j++) {
        float4 C = make_float4(0.f, 0.f, 0.f, 0.f);
        if (oq < 13) C = *(const float4*)(xsh + (p0 + j) * NPAD + (oq << 2));
        C.x *= 1.f + sigmf(Z[j].x); C.y *= 1.f + sigmf(Z[j].y);
        C.z *= 1.f + sigmf(Z[j].z); C.w *= 1.f + sigmf(Z[j].w);
        float inv = 1.f / (grp16_sum(C.x + C.y + C.z + C.w) + 1e-7f);
        if (oq < 13) {
            float* co = g_comb + (size_t)(pg0 + p0 + j) * NPAD + (oq << 2);
            *(float4*)(co) = make_float4(C.x * inv, C.y * inv, C.z * inv, C.w * inv);
        }
    }
}

// ---------------- k_reduce: weighted neighborhood reduction -----------------
// fully unrolled; compile-time dy/dx pairs become SELs on `half`.
__global__ __launch_bounds__(256) void k_reduce() {
    __shared__ float cws[8][NPAD];
    const int tid = threadIdx.x;
    const int wid = tid >> 5, lane = tid & 31;
    const int half = lane >> 4, q = lane & 15;
    float* cw = cws[wid];

    const int pg = (blockIdx.x << 3) + wid;
    const int b  = pg / HWSZ;
    const int hw = pg - b * HWSZ;
    const int h  = hw / WW, w = hw - h * WW;

    if (lane < 13)
        *(float4*)(cw + (lane << 2)) =
            *(const float4*)(g_comb + (size_t)pg * NPAD + (lane << 2));
    __syncwarp();

    const char* rowc = (const char*)(g_spat + (size_t)pg * CH) + q * 16;
    const float* cwh = cw + half;
    float a0 = 0.f, a1 = 0.f, a2 = 0.f, a3 = 0.f;
#pragma unroll
    for (int k = 0; k < 25; k++) {
        const int nA = 2 * k, nB = 2 * k + 1;
        const int dyA = nA / 7 - RAD;
        const int dyB = (nB < NN) ? nB / 7 - RAD : 1000;
        const int dxA = nA - (nA / 7) * 7 - RAD;
        const int dxB = nB - (nB / 7) * 7 - RAD;
        const int offA = (dyA * WW + dxA) * (CH * 4);
        const int offB = (dyB * WW + dxB) * (CH * 4);
        const int dy  = half ? dyB : dyA;
        const int dx  = half ? dxB : dxA;
        const int off = half ? offB : offA;
        const int hh = h + dy, ww2 = w + dx;
        if (((unsigned)hh < (unsigned)HH) && ((unsigned)ww2 < (unsigned)WW)) {
            const float cn = cwh[2 * k];
            const float4 sv = *(const float4*)(rowc + off);
            a0 = fmaf(sv.x, cn, a0); a1 = fmaf(sv.y, cn, a1);
            a2 = fmaf(sv.z, cn, a2); a3 = fmaf(sv.w, cn, a3);
        }
    }
    a0 += __shfl_xor_sync(0xffffffffu, a0, 16);
    a1 += __shfl_xor_sync(0xffffffffu, a1, 16);
    a2 += __shfl_xor_sync(0xffffffffu, a2, 16);
    a3 += __shfl_xor_sync(0xffffffffu, a3, 16);
    if (half == 0)
        ((float4*)(g_mid + (size_t)pg * CH))[q] = make_float4(a0, a1, a2, a3);
}

// ---------------- output_proj: conv1x1 -> LN -> conv1x1 ---------------------
// 64 px/block, thread = 4 px x 4 channels, grid 392. g_mid NHWC -> out NCHW.
__global__ __launch_bounds__(256) void k_outproj(
    const float* __restrict__ b1,
    const float* __restrict__ gg, const float* __restrict__ be,
    const float* __restrict__ b2,
    float* __restrict__ out) {
    extern __shared__ float sm[];
    float* W1t = sm;                // [64][68]
    float* W2t = W1t + 64 * 68;     // [64][68]
    float* xsh = W2t + 64 * 68;     // [64][68] x[p][c], aliased as y after conv1
    const int tid = threadIdx.x;
    for (int i = tid; i < 1088; i += 256) {
        ((float4*)W1t)[i] = ((const float4*)gWop1)[i];
        ((float4*)W2t)[i] = ((const float4*)gWop2)[i];
    }
    const int oq = tid & 15, p0 = (tid >> 4) << 2;
    const float4 rb1 = *(const float4*)(b1 + oq * 4);
    const float4 rg  = *(const float4*)(gg + oq * 4);
    const float4 rbe = *(const float4*)(be + oq * 4);
    const float4 rb2 = *(const float4*)(b2 + oq * 4);

    const int pg0   = blockIdx.x << 6;
    const int b     = pg0 / HWSZ;
    const int pbase = pg0 - b * HWSZ;
    const float* inb = g_mid + (size_t)pg0 * CH;
    for (int i = tid; i < 1024; i += 256) {
        int p = i >> 4, cq = (i & 15) << 2;
        *(float4*)(xsh + p * 68 + cq) = *(const float4*)(inb + p * CH + cq);
    }
    __syncthreads();

    float4 A[4];
#pragma unroll
    for (int j = 0; j < 4; j++) A[j] = rb1;
#pragma unroll 8
    for (int c = 0; c < 64; c++) {
        float4 wv = *(const float4*)(W1t + c * 68 + (oq << 2));
#pragma unroll
        for (int j = 0; j < 4; j++) {
            float xv = xsh[(p0 + j) * 68 + c];
            FMA4W(A[j], wv, xv)
        }
    }
#pragma unroll
    for (int j = 0; j < 4; j++) A[j] = ln_apply(A[j], rg, rbe, 1.f / 64.f);
    __syncwarp();
#pragma unroll
    for (int j = 0; j < 4; j++)
        *(float4*)(xsh + (p0 + j) * 68 + (oq << 2)) = A[j];
    __syncwarp();

    float4 Z[4];
#pragma unroll
    for (int j = 0; j < 4; j++) Z[j] = rb2;
#pragma unroll 8
    for (int c = 0; c < 64; c++) {
        float4 wv = *(const float4*)(W2t + c * 68 + (oq << 2));
#pragma unroll
        for (int j = 0; j < 4; j++) {
            float xv = xsh[(p0 + j) * 68 + c];
            FMA4W(Z[j], wv, xv)
        }
    }
    float* outb = out + (size_t)b * CH * HWSZ + (size_t)(oq * 4) * HWSZ + pbase + p0;
    *(float4*)(outb)            = make_float4(Z[0].x, Z[1].x, Z[2].x, Z[3].x);
    *(float4*)(outb + HWSZ)     = make_float4(Z[0].y, Z[1].y, Z[2].y, Z[3].y);
    *(float4*)(outb + 2 * HWSZ) = make_float4(Z[0].z, Z[1].z, Z[2].z, Z[3].z);
    *(float4*)(outb + 3 * HWSZ) = make_float4(Z[0].w, Z[1].w, Z[2].w, Z[3].w);
}

// ---------------- launch ----------------------------------------------------
extern "C" void kernel_launch(void* const* d_in, const int* in_sizes, int n_in,
                              void* d_out, int out_size) {
    (void)in_sizes; (void)n_in; (void)out_size;
    const float* spatial  = (const float*)d_in[0];
    const float* semantic = (const float*)d_in[1];
    const float* rp_w1 = (const float*)d_in[2];
    const float* rp_b1 = (const float*)d_in[3];
    const float* rp_g  = (const float*)d_in[4];
    const float* rp_be = (const float*)d_in[5];
    const float* rp_w2 = (const float*)d_in[6];
    const float* rp_b2 = (const float*)d_in[7];
    const float* fx_w1 = (const float*)d_in[8];
    const float* fx_b1 = (const float*)d_in[9];
    const float* fx_g  = (const float*)d_in[10];
    const float* fx_be = (const float*)d_in[11];
    const float* fx_w2 = (const float*)d_in[12];
    const float* fx_b2 = (const float*)d_in[13];
    const float* op_w1 = (const float*)d_in[14];
    const float* op_b1 = (const float*)d_in[15];
    const float* op_g  = (const float*)d_in[16];
    const float* op_be = (const float*)d_in[17];
    const float* op_w2 = (const float*)d_in[18];
    const float* op_b2 = (const float*)d_in[19];
    const float* sigma = (const float*)d_in[20];
    float* out = (float*)d_out;

    const int SMEM_RP = (3 * 64 * 68 + 64 * 64) * 4;                  // 68608 B
    const int SMEM_FX = (2 * 49 * 68 + 2 * 64 * NPAD + 4 * 64) * 4;   // 54304 B
    const int SMEM_OP = (2 * 64 * 68 + 64 * 68) * 4;                  // 52224 B
    cudaFuncSetAttribute(k_rangeproj, cudaFuncAttributeMaxDynamicSharedMemorySize, SMEM_RP);
    cudaFuncSetAttribute(k_fixup,     cudaFuncAttributeMaxDynamicSharedMemorySize, SMEM_FX);
    cudaFuncSetAttribute(k_outproj,   cudaFuncAttributeMaxDynamicSharedMemorySize, SMEM_OP);

    k_prep<<<7 * 17, 256>>>(rp_w1, rp_w2, fx_w1, fx_w2, op_w1, op_w2);
    k_transpose<<<BATCH * (HWSZ / 32), 256>>>(spatial);
    k_rangeproj<<<NPIX / 64, 256, SMEM_RP>>>(semantic, rp_b1, rp_g, rp_be, rp_b2);
    k_weights<<<NPIX / 8, 256>>>(sigma);
    k_fixup<<<NPIX / 64, 256, SMEM_FX>>>(fx_b1, fx_g, fx_be, fx_b2);
    k_reduce<<<NPIX / 8, 256>>>();
    k_outproj<<<NPIX / 64, 256, SMEM_OP>>>(op_b1, op_g, op_be, op_b2, out);
}

// round 15
// speedup vs baseline: 2.1135x; 1.0026x over previous
#include <cuda_runtime.h>
#include <math.h>

#define BATCH 2
#define CH    64
#define HH    112
#define WW    112
#define HWSZ  (HH*WW)
#define NPIX  (BATCH*HWSZ)
#define RAD   3
#define NN    49
#define NPAD  52

__device__ __align__(256) float g_px  [NPIX*CH];    // range-projected, NHWC
__device__ __align__(256) float g_spat[NPIX*CH];    // spatial feats, NHWC
__device__ __align__(256) float g_mid [NPIX*CH];    // pre-output_proj, NHWC
__device__ __align__(256) float g_fxs [NPIX*CH];    // fixup semantic partial (64-pad)
__device__ __align__(256) float g_comb[NPIX*NPAD];  // bilateral weights (52-pad)
__device__ __align__(256) float g_nrm [NPIX];       // ||px[p]||^2

// pre-transposed, padded weight matrices (filled by k_prep each launch)
__device__ __align__(256) float gWrp1[64*68];
__device__ __align__(256) float gWrp2[64*68];
__device__ __align__(256) float gWfse[64*68];
__device__ __align__(256) float gWfx1[49*68];
__device__ __align__(256) float gWfx2[49*68];
__device__ __align__(256) float gWop1[64*68];
__device__ __align__(256) float gWop2[64*68];

__device__ __forceinline__ float grp16_sum(float v) {
#pragma unroll
    for (int off = 8; off > 0; off >>= 1)
        v += __shfl_xor_sync(0xffffffffu, v, off);
    return v;
}
__device__ __forceinline__ float sigmf(float x) {
    return 1.f / (1.f + __expf(-x));
}

#define FMA4W(Acc, W, X) { \
    Acc.x = fmaf(W.x, X, Acc.x); Acc.y = fmaf(W.y, X, Acc.y); \
    Acc.z = fmaf(W.z, X, Acc.z); Acc.w = fmaf(W.w, X, Acc.w); }

__device__ __forceinline__ float4 ln_apply(float4 A, float4 g, float4 be, float invn) {
    float s1 = grp16_sum(A.x + A.y + A.z + A.w);
    float s2 = grp16_sum(A.x*A.x + A.y*A.y + A.z*A.z + A.w*A.w);
    float u  = s1 * invn;
    float rs = rsqrtf(fmaxf(s2 * invn - u * u, 0.f) + 1e-6f);
    return make_float4(fmaf(g.x, (A.x - u) * rs, be.x),
                       fmaf(g.y, (A.y - u) * rs, be.y),
                       fmaf(g.z, (A.z - u) * rs, be.z),
                       fmaf(g.w, (A.w - u) * rs, be.w));
}
__device__ __forceinline__ float4 silu4(float4 v) {
    return make_float4(v.x * sigmf(v.x), v.y * sigmf(v.y),
                       v.z * sigmf(v.z), v.w * sigmf(v.w));
}

// ---------------- k_prep: transpose/pad all weights once --------------------
__global__ __launch_bounds__(256) void k_prep(
    const float* __restrict__ rp_w1, const float* __restrict__ rp_w2,
    const float* __restrict__ fx_w1, const float* __restrict__ fx_w2,
    const float* __restrict__ op_w1, const float* __restrict__ op_w2) {
    const int seg = blockIdx.x / 17;
    const int idx = (blockIdx.x - seg * 17) * 256 + threadIdx.x;  // < 4352
    const int row = idx / 68, o = idx - row * 68;
    switch (seg) {
    case 0: gWrp1[idx] = (o < 64) ? rp_w1[o * 64 + row] : 0.f; break;
    case 1: gWrp2[idx] = (o < 64) ? rp_w2[o * 64 + row] : 0.f; break;
    case 2: gWfse[idx] = (o < NN) ? fx_w1[o * 113 + 49 + row] : 0.f; break;
    case 3: if (idx < 49 * 68) gWfx1[idx] = (o < NN) ? fx_w1[o * 113 + row] : 0.f; break;
    case 4: if (idx < 49 * 68) gWfx2[idx] = (o < NN) ? fx_w2[o * NN + row] : 0.f; break;
    case 5: gWop1[idx] = (o < 64) ? op_w1[o * 64 + row] : 0.f; break;
    default: gWop2[idx] = (o < 64) ? op_w2[o * 64 + row] : 0.f; break;
    }
}

// ---------------- NCHW -> NHWC transpose of spatial feats -------------------
__global__ __launch_bounds__(256) void k_transpose(const float* __restrict__ in) {
    __shared__ float t[64 * 33];
    const int blk   = blockIdx.x;
    const int b     = blk / (HWSZ / 32);
    const int pbase = (blk - b * (HWSZ / 32)) * 32;
    const float* inb = in + (size_t)b * CH * HWSZ;
    for (int i = threadIdx.x; i < 2048; i += 256) {
        int c = i >> 5, p = i & 31;
        t[c * 33 + p] = inb[c * HWSZ + pbase + p];
    }
    __syncthreads();
    float* outb = g_spat + ((size_t)b * HWSZ + pbase) * CH;
    for (int i = threadIdx.x; i < 2048; i += 256) {
        int p = i >> 6, c = i & 63;
        outb[p * CH + c] = t[c * 33 + p];
    }
}

// ---------------- range_proj + fixup-semantic GEMM + norms ------------------
// 64 px/block, thread = 4 px x 4 channels, grid 392.
__global__ __launch_bounds__(256) void k_rangeproj(
    const float* __restrict__ sem,
    const float* __restrict__ b1,
    const float* __restrict__ gg, const float* __restrict__ be,
    const float* __restrict__ b2) {
    extern __shared__ float sm[];
    float* W1t = sm;                 // [64][68]
    float* W2t = W1t + 64 * 68;      // [64][68]
    float* Wf  = W2t + 64 * 68;      // [64][68]
    float* xs  = Wf  + 64 * 68;      // [64][64] x[c][p]; later y[p][c] stride 64
    const int tid = threadIdx.x;
    for (int i = tid; i < 1088; i += 256) {
        ((float4*)W1t)[i] = ((const float4*)gWrp1)[i];
        ((float4*)W2t)[i] = ((const float4*)gWrp2)[i];
        ((float4*)Wf )[i] = ((const float4*)gWfse)[i];
    }
    const int oq = tid & 15, p0 = (tid >> 4) << 2;
    const float4 rb1 = *(const float4*)(b1 + oq * 4);
    const float4 rg  = *(const float4*)(gg + oq * 4);
    const float4 rbe = *(const float4*)(be + oq * 4);
    const float4 rb2 = *(const float4*)(b2 + oq * 4);

    const int pg0   = blockIdx.x << 6;
    const int b     = pg0 / HWSZ;
    const int pbase = pg0 - b * HWSZ;
    const float* inb = sem + (size_t)b * CH * HWSZ + pbase;
    for (int i = tid; i < 1024; i += 256) {
        int c = i >> 4, q4 = (i & 15) << 2;
        *(float4*)(xs + c * 64 + q4) = *(const float4*)(inb + c * HWSZ + q4);
    }
    __syncthreads();

    float4 A[4];
    // fixup-semantic GEMM first
#pragma unroll
    for (int j = 0; j < 4; j++) A[j] = make_float4(0.f, 0.f, 0.f, 0.f);
#pragma unroll 8
    for (int c = 0; c < 64; c++) {
        float4 wv = *(const float4*)(Wf + c * 68 + (oq << 2));
        float4 xv = *(const float4*)(xs + (c << 6) + p0);
        FMA4W(A[0], wv, xv.x) FMA4W(A[1], wv, xv.y)
        FMA4W(A[2], wv, xv.z) FMA4W(A[3], wv, xv.w)
    }
    {
        float* fo = g_fxs + (size_t)(pg0 + p0) * CH + (oq << 2);
#pragma unroll
        for (int j = 0; j < 4; j++) *(float4*)(fo + j * CH) = A[j];
    }

    // conv1
#pragma unroll
    for (int j = 0; j < 4; j++) A[j] = rb1;
#pragma unroll 8
    for (int c = 0; c < 64; c++) {
        float4 wv = *(const float4*)(W1t + c * 68 + (oq << 2));
        float4 xv = *(const float4*)(xs  + (c << 6) + p0);
        FMA4W(A[0], wv, xv.x) FMA4W(A[1], wv, xv.y)
        FMA4W(A[2], wv, xv.z) FMA4W(A[3], wv, xv.w)
    }
#pragma unroll
    for (int j = 0; j < 4; j++) A[j] = silu4(ln_apply(A[j], rg, rbe, 1.f / 64.f));
    __syncthreads();              // all xs reads complete
#pragma unroll
    for (int j = 0; j < 4; j++)
        *(float4*)(xs + (p0 + j) * 64 + (oq << 2)) = A[j];
    __syncwarp();                 // y rows are 16-lane-group private

    // conv2
    float4 Z[4];
#pragma unroll
    for (int j = 0; j < 4; j++) Z[j] = rb2;
#pragma unroll 8
    for (int c = 0; c < 64; c++) {
        float4 wv = *(const float4*)(W2t + c * 68 + (oq << 2));
#pragma unroll
        for (int j = 0; j < 4; j++) {
            float xv = xs[(p0 + j) * 64 + c];
            FMA4W(Z[j], wv, xv)
        }
    }
    {
        float* po = g_px + (size_t)(pg0 + p0) * CH + (oq << 2);
#pragma unroll
        for (int j = 0; j < 4; j++) *(float4*)(po + j * CH) = Z[j];
    }
    // norms: ||px[p]||^2 for the bilateral dot-product form
#pragma unroll
    for (int j = 0; j < 4; j++) {
        float s = grp16_sum(Z[j].x*Z[j].x + Z[j].y*Z[j].y +
                            Z[j].z*Z[j].z + Z[j].w*Z[j].w);
        if (oq == 0) g_nrm[pg0 + p0 + j] = s;
    }
}

// ---------------- k_weights: bilateral weights, 4-px register tile ----------
// Warp = 4 adjacent pixels; walks the 7x10 union of their neighborhoods once.
// Groups of 8 lanes take rows with the SAME qx (warp-uniform j-windows).
__global__ __launch_bounds__(256) void k_weights(const float* __restrict__ sigp) {
    __shared__ int4   tA[80];   // {byteOff, K, dy_bounds, qx_bounds}
    __shared__ float4 tD[80];   // spatial d2s*inv2sig for j=0..3
    __shared__ int    tW[80];   // window qx (uniform within each 8-slot block)
    __shared__ float  cws[8][4][56];
    const int tid = threadIdx.x;
    if (tid < 80) {
        const int qxi = tid >> 3, t = tid & 7;
        const int qx  = qxi - 3;                 // -3..6
        const bool dummy = (t == 7);
        const int dy  = dummy ? 0 : t - 3;       // -3..3
        tA[tid] = make_int4((dy * WW + (dummy ? 0 : qx)) * (CH * 4),
                            (dy + 3) * 7 + qx + 3,
                            dummy ? 100000 : dy,
                            dummy ? 0 : qx);
        tW[tid] = qx;                            // uniform per 8-block
        const float s = *sigp;
        const float i2s = 0.5f / (s * s);
        float4 dd;
        dd.x = (float)(dy * dy + qx * qx) * i2s;
        dd.y = (float)(dy * dy + (qx - 1) * (qx - 1)) * i2s;
        dd.z = (float)(dy * dy + (qx - 2) * (qx - 2)) * i2s;
        dd.w = (float)(dy * dy + (qx - 3) * (qx - 3)) * i2s;
        tD[tid] = dd;
    }
    {   // zero the per-warp weight buffers
        float* cz = &cws[0][0][0];
        for (int i = tid; i < 8 * 4 * 56; i += 256) cz[i] = 0.f;
    }
    __syncthreads();

    const int wid = tid >> 5, lane = tid & 31;
    const int g = lane >> 3, r = lane & 7;
    const int pg0 = (blockIdx.x * 8 + wid) * 4;
    const int b   = pg0 / HWSZ;
    const int hw  = pg0 - b * HWSZ;
    const int h   = hw / WW, w0 = hw - h * WW;
    float (*cw)[56] = cws[wid];

    const char* rowp = (const char*)(g_px + (size_t)pg0 * CH) + r * 32;
    float4 cA[4], cB[4];
    float  cb[4];
#pragma unroll
    for (int j = 0; j < 4; j++) {
        cA[j] = *(const float4*)(rowp + j * 256);
        cB[j] = *(const float4*)(rowp + j * 256 + 16);
        cb[j] = g_nrm[pg0 + j];
    }

#pragma unroll
    for (int it = 0; it < 20; it++) {
        const int  s = it * 4 + g;
        const int4 e = tA[s];
        const int  wqx = tW[s];
        const bool valid = ((unsigned)(h + e.z) < (unsigned)HH) &&
                           ((unsigned)(w0 + e.w) < (unsigned)WW);
        float4 nv0 = make_float4(0.f, 0.f, 0.f, 0.f), nv1 = nv0;
        float  Sn = 0.f;
        if (valid) {
            nv0 = *(const float4*)(rowp + e.x);
            nv1 = *(const float4*)(rowp + e.x + 16);
            Sn  = g_nrm[pg0 + (e.x >> 8)];
        }
        const float4 dd = tD[s];
#define DOJ(J, DSS) \
        if ((unsigned)(wqx - J + 3) <= 6u) { \
            float d = cA[J].x * nv0.x; \
            d = fmaf(cA[J].y, nv0.y, d); d = fmaf(cA[J].z, nv0.z, d); \
            d = fmaf(cA[J].w, nv0.w, d); d = fmaf(cB[J].x, nv1.x, d); \
            d = fmaf(cB[J].y, nv1.y, d); d = fmaf(cB[J].z, nv1.z, d); \
            d = fmaf(cB[J].w, nv1.w, d); \
            d += __shfl_xor_sync(0xffffffffu, d, 4); \
            d += __shfl_xor_sync(0xffffffffu, d, 2); \
            d += __shfl_xor_sync(0xffffffffu, d, 1); \
            if (valid && r == 0) { \
                float arg = fminf(fmaf(d, 1.f / 64.f, \
                                       -(Sn + cb[J]) * (1.f / 128.f)), 0.f) - DSS; \
                cw[J][e.y - J] = __expf(arg); \
            } \
        }
        DOJ(0, dd.x) DOJ(1, dd.y) DOJ(2, dd.z) DOJ(3, dd.w)
#undef DOJ
    }
    __syncwarp();
#pragma unroll
    for (int j = 0; j < 4; j++)
        if (lane < 13)
            *(float4*)(g_comb + (size_t)(pg0 + j) * NPAD + (lane << 2)) =
                *(const float4*)(&cw[j][lane << 2]);
}

// ---------------- k_fixup: batched fixup MLP + gate + normalize -------------
// 64 px/block, thread = 4 px x 4 outs, grid 392.
__global__ __launch_bounds__(256) void k_fixup(
    const float* __restrict__ fxb1,
    const float* __restrict__ fxg,  const float* __restrict__ fxbe,
    const float* __restrict__ fxb2) {
    extern __shared__ float sm[];
    float* W1t = sm;              // [49][68]
    float* W2t = W1t + 49 * 68;   // [49][68]
    float* xsh = W2t + 49 * 68;   // [64][52]
    float* ysh = xsh + 64 * NPAD; // [64][52]
    float* sb1 = ysh + 64 * NPAD;
    float* sg  = sb1 + 64;
    float* sbe = sg  + 64;
    float* sb2 = sbe + 64;
    const int tid = threadIdx.x;
    for (int i = tid; i < 833; i += 256) {
        ((float4*)W1t)[i] = ((const float4*)gWfx1)[i];
        ((float4*)W2t)[i] = ((const float4*)gWfx2)[i];
    }
    if (tid < 64) {
        sb1[tid] = (tid < NN) ? fxb1[tid] : 0.f;
        sg [tid] = (tid < NN) ? fxg [tid] : 0.f;
        sbe[tid] = (tid < NN) ? fxbe[tid] : 0.f;
        sb2[tid] = (tid < NN) ? fxb2[tid] : 0.f;
    }
    const int pg0 = blockIdx.x << 6;
    const float* cin = g_comb + (size_t)pg0 * NPAD;
    for (int i = tid; i < 64 * 13; i += 256) {
        int p = i / 13, j4 = (i - p * 13) << 2;
        *(float4*)(xsh + p * NPAD + j4) = *(const float4*)(cin + p * NPAD + j4);
    }
    __syncthreads();

    const int oq = tid & 15, p0 = (tid >> 4) << 2;
    const float4 b1v = *(const float4*)(sb1 + (oq << 2));
    const float4 gv  = *(const float4*)(sg  + (oq << 2));
    const float4 bev = *(const float4*)(sbe + (oq << 2));
    const float4 b2v = *(const float4*)(sb2 + (oq << 2));

    float4 A[4];
    {
        const float* fxp = g_fxs + (size_t)(pg0 + p0) * CH + (oq << 2);
#pragma unroll
        for (int j = 0; j < 4; j++) {
            float4 F = *(const float4*)(fxp + j * CH);
            A[j] = make_float4(b1v.x + F.x, b1v.y + F.y, b1v.z + F.z, b1v.w + F.w);
        }
    }
#pragma unroll 7
    for (int n = 0; n < NN; n++) {
        float4 wv = *(const float4*)(W1t + n * 68 + (oq << 2));
#pragma unroll
        for (int j = 0; j < 4; j++) {
            float xv = xsh[(p0 + j) * NPAD + n];
            FMA4W(A[j], wv, xv)
        }
    }
#pragma unroll
    for (int j = 0; j < 4; j++) {
        A[j] = silu4(ln_apply(A[j], gv, bev, 1.f / 49.f));
        if (oq < 13) *(float4*)(ysh + (p0 + j) * NPAD + (oq << 2)) = A[j];
    }
    __syncwarp();

    float4 Z[4];
#pragma unroll
    for (int j = 0; j < 4; j++) Z[j] = b2v;
#pragma unroll 7
    for (int n = 0; n < NN; n++) {
        float4 wv = *(const float4*)(W2t + n * 68 + (oq << 2));
#pragma unroll
        for (int j = 0; j < 4; j++) {
            float yv = ysh[(p0 + j) * NPAD + n];
            FMA4W(Z[j], wv, yv)
        }
    }
#pragma unroll
    for (int j = 0; j < 4; j++) {
        float4 C = make_float4(0.f, 0.f, 0.f, 0.f);
        if (oq < 13) C = *(const float4*)(xsh + (p0 + j) * NPAD + (oq << 2));
        C.x *= 1.f + sigmf(Z[j].x); C.y *= 1.f + sigmf(Z[j].y);
        C.z *= 1.f + sigmf(Z[j].z); C.w *= 1.f + sigmf(Z[j].w);
        float inv = 1.f / (grp16_sum(C.x + C.y + C.z + C.w) + 1e-7f);
        if (oq < 13) {
            float* co = g_comb + (size_t)(pg0 + p0 + j) * NPAD + (oq << 2);
            *(float4*)(co) = make_float4(C.x * inv, C.y * inv, C.z * inv, C.w * inv);
        }
    }
}

// ---------------- k_reduce: weighted neighborhood reduction -----------------
__global__ __launch_bounds__(256) void k_reduce() {
    __shared__ float cws[8][NPAD];
    const int tid = threadIdx.x;
    const int wid = tid >> 5, lane = tid & 31;
    const int half = lane >> 4, q = lane & 15;
    float* cw = cws[wid];

    const int pg = (blockIdx.x << 3) + wid;
    const int b  = pg / HWSZ;
    const int hw = pg - b * HWSZ;
    const int h  = hw / WW, w = hw - h * WW;

    if (lane < 13)
        *(float4*)(cw + (lane << 2)) =
            *(const float4*)(g_comb + (size_t)pg * NPAD + (lane << 2));
    __syncwarp();

    const char* rowc = (const char*)(g_spat + (size_t)pg * CH) + q * 16;
    const float* cwh = cw + half;
    float a0 = 0.f, a1 = 0.f, a2 = 0.f, a3 = 0.f;
#pragma unroll
    for (int k = 0; k < 25; k++) {
        const int nA = 2 * k, nB = 2 * k + 1;
        const int dyA = nA / 7 - RAD;
        const int dyB = (nB < NN) ? nB / 7 - RAD : 1000;
        const int dxA = nA - (nA / 7) * 7 - RAD;
        const int dxB = nB - (nB / 7) * 7 - RAD;
        const int offA = (dyA * WW + dxA) * (CH * 4);
        const int offB = (dyB * WW + dxB) * (CH * 4);
        const int dy  = half ? dyB : dyA;
        const int dx  = half ? dxB : dxA;
        const int off = half ? offB : offA;
        const int hh = h + dy, ww2 = w + dx;
        if (((unsigned)hh < (unsigned)HH) && ((unsigned)ww2 < (unsigned)WW)) {
            const float cn = cwh[2 * k];
            const float4 sv = *(const float4*)(rowc + off);
            a0 = fmaf(sv.x, cn, a0); a1 = fmaf(sv.y, cn, a1);
            a2 = fmaf(sv.z, cn, a2); a3 = fmaf(sv.w, cn, a3);
        }
    }
    a0 += __shfl_xor_sync(0xffffffffu, a0, 16);
    a1 += __shfl_xor_sync(0xffffffffu, a1, 16);
    a2 += __shfl_xor_sync(0xffffffffu, a2, 16);
    a3 += __shfl_xor_sync(0xffffffffu, a3, 16);
    if (half == 0)
        ((float4*)(g_mid + (size_t)pg * CH))[q] = make_float4(a0, a1, a2, a3);
}

// ---------------- output_proj: conv1x1 -> LN -> conv1x1 ---------------------
// 64 px/block, thread = 4 px x 4 channels, grid 392. g_mid NHWC -> out NCHW.
__global__ __launch_bounds__(256) void k_outproj(
    const float* __restrict__ b1,
    const float* __restrict__ gg, const float* __restrict__ be,
    const float* __restrict__ b2,
    float* __restrict__ out) {
    extern __shared__ float sm[];
    float* W1t = sm;                // [64][68]
    float* W2t = W1t + 64 * 68;     // [64][68]
    float* xsh = W2t + 64 * 68;     // [64][68] x[p][c], aliased as y after conv1
    const int tid = threadIdx.x;
    for (int i = tid; i < 1088; i += 256) {
        ((float4*)W1t)[i] = ((const float4*)gWop1)[i];
        ((float4*)W2t)[i] = ((const float4*)gWop2)[i];
    }
    const int oq = tid & 15, p0 = (tid >> 4) << 2;
    const float4 rb1 = *(const float4*)(b1 + oq * 4);
    const float4 rg  = *(const float4*)(gg + oq * 4);
    const float4 rbe = *(const float4*)(be + oq * 4);
    const float4 rb2 = *(const float4*)(b2 + oq * 4);

    const int pg0   = blockIdx.x << 6;
    const int b     = pg0 / HWSZ;
    const int pbase = pg0 - b * HWSZ;
    const float* inb = g_mid + (size_t)pg0 * CH;
    for (int i = tid; i < 1024; i += 256) {
        int p = i >> 4, cq = (i & 15) << 2;
        *(float4*)(xsh + p * 68 + cq) = *(const float4*)(inb + p * CH + cq);
    }
    __syncthreads();

    float4 A[4];
#pragma unroll
    for (int j = 0; j < 4; j++) A[j] = rb1;
#pragma unroll 8
    for (int c = 0; c < 64; c++) {
        float4 wv = *(const float4*)(W1t + c * 68 + (oq << 2));
#pragma unroll
        for (int j = 0; j < 4; j++) {
            float xv = xsh[(p0 + j) * 68 + c];
            FMA4W(A[j], wv, xv)
        }
    }
#pragma unroll
    for (int j = 0; j < 4; j++) A[j] = ln_apply(A[j], rg, rbe, 1.f / 64.f);
    __syncwarp();
#pragma unroll
    for (int j = 0; j < 4; j++)
        *(float4*)(xsh + (p0 + j) * 68 + (oq << 2)) = A[j];
    __syncwarp();

    float4 Z[4];
#pragma unroll
    for (int j = 0; j < 4; j++) Z[j] = rb2;
#pragma unroll 8
    for (int c = 0; c < 64; c++) {
        float4 wv = *(const float4*)(W2t + c * 68 + (oq << 2));
#pragma unroll
        for (int j = 0; j < 4; j++) {
            float xv = xsh[(p0 + j) * 68 + c];
            FMA4W(Z[j], wv, xv)
        }
    }
    float* outb = out + (size_t)b * CH * HWSZ + (size_t)(oq * 4) * HWSZ + pbase + p0;
    *(float4*)(outb)            = make_float4(Z[0].x, Z[1].x, Z[2].x, Z[3].x);
    *(float4*)(outb + HWSZ)     = make_float4(Z[0].y, Z[1].y, Z[2].y, Z[3].y);
    *(float4*)(outb + 2 * HWSZ) = make_float4(Z[0].z, Z[1].z, Z[2].z, Z[3].z);
    *(float4*)(outb + 3 * HWSZ) = make_float4(Z[0].w, Z[1].w, Z[2].w, Z[3].w);
}

// ---------------- launch ----------------------------------------------------
extern "C" void kernel_launch(void* const* d_in, const int* in_sizes, int n_in,
                              void* d_out, int out_size) {
    (void)in_sizes; (void)n_in; (void)out_size;
    const float* spatial  = (const float*)d_in[0];
    const float* semantic = (const float*)d_in[1];
    const float* rp_w1 = (const float*)d_in[2];
    const float* rp_b1 = (const float*)d_in[3];
    const float* rp_g  = (const float*)d_in[4];
    const float* rp_be = (const float*)d_in[5];
    const float* rp_w2 = (const float*)d_in[6];
    const float* rp_b2 = (const float*)d_in[7];
    const float* fx_w1 = (const float*)d_in[8];
    const float* fx_b1 = (const float*)d_in[9];
    const float* fx_g  = (const float*)d_in[10];
    const float* fx_be = (const float*)d_in[11];
    const float* fx_w2 = (const float*)d_in[12];
    const float* fx_b2 = (const float*)d_in[13];
    const float* op_w1 = (const float*)d_in[14];
    const float* op_b1 = (const float*)d_in[15];
    const float* op_g  = (const float*)d_in[16];
    const float* op_be = (const float*)d_in[17];
    const float* op_w2 = (const float*)d_in[18];
    const float* op_b2 = (const float*)d_in[19];
    const float* sigma = (const float*)d_in[20];
    float* out = (float*)d_out;

    const int SMEM_RP = (3 * 64 * 68 + 64 * 64) * 4;                  // 68608 B
    const int SMEM_FX = (2 * 49 * 68 + 2 * 64 * NPAD + 4 * 64) * 4;   // 54304 B
    const int SMEM_OP = (2 * 64 * 68 + 64 * 68) * 4;                  // 52224 B
    cudaFuncSetAttribute(k_rangeproj, cudaFuncAttributeMaxDynamicSharedMemorySize, SMEM_RP);
    cudaFuncSetAttribute(k_fixup,     cudaFuncAttributeMaxDynamicSharedMemorySize, SMEM_FX);
    cudaFuncSetAttribute(k_outproj,   cudaFuncAttributeMaxDynamicSharedMemorySize, SMEM_OP);

    k_prep<<<7 * 17, 256>>>(rp_w1, rp_w2, fx_w1, fx_w2, op_w1, op_w2);
    k_transpose<<<BATCH * (HWSZ / 32), 256>>>(spatial);
    k_rangeproj<<<NPIX / 64, 256, SMEM_RP>>>(semantic, rp_b1, rp_g, rp_be, rp_b2);
    k_weights<<<NPIX / 32, 256>>>(sigma);
    k_fixup<<<NPIX / 64, 256, SMEM_FX>>>(fx_b1, fx_g, fx_be, fx_b2);
    k_reduce<<<NPIX / 8, 256>>>();
    k_outproj<<<NPIX / 64, 256, SMEM_OP>>>(op_b1, op_g, op_be, op_b2, out);
}